// round 3
// baseline (speedup 1.0000x reference)
#include <cuda_runtime.h>
#include <cstdint>
#include <float.h>

// Problem constants
#define Bn 32768
#define Ln 4
#define Kn 2048
#define Dn 512

// Output layout (float32, flattened tuple in return order):
//   output [B,L], r [B,L,D], e [B,L,D], z_hat [B,D], count [1]
constexpr size_t OFF_OUT = 0;
constexpr size_t OFF_R   = (size_t)Bn * Ln;                       // 131072
constexpr size_t OFF_E   = OFF_R + (size_t)Bn * Ln * Dn;          // 67239936
constexpr size_t OFF_Z   = OFF_E + (size_t)Bn * Ln * Dn;          // 134348800
constexpr size_t OFF_CNT = OFF_Z + (size_t)Bn * Dn;               // 151126016

// Scratch (device globals; no allocations allowed)
__device__ int   g_idx[Bn * Ln];
__device__ int   g_hist[Ln * Kn];
__device__ float g_cnorm[Ln * Kn];
__device__ float g_xnorm[Bn];

// ---------------- packed f32x2 helpers ----------------
__device__ __forceinline__ unsigned long long pack2(float a, float b) {
    unsigned long long r;
    asm("mov.b64 %0, {%1, %2};" : "=l"(r) : "f"(a), "f"(b));
    return r;
}
__device__ __forceinline__ unsigned long long fma2(unsigned long long a,
                                                   unsigned long long b,
                                                   unsigned long long c) {
    unsigned long long d;
    asm("fma.rn.f32x2 %0, %1, %2, %3;" : "=l"(d) : "l"(a), "l"(b), "l"(c));
    return d;
}
__device__ __forceinline__ void unpack2(unsigned long long p, float& a, float& b) {
    asm("mov.b64 {%0, %1}, %2;" : "=f"(a), "=f"(b) : "l"(p));
}

// ---------------- XLA-GPU-style f32 row-norm of a 512-float row ----------------
// Replicates XLA's row-reduction schedule bitwise:
//   256 threads, vector=2: thread t accumulates fl(fl(x[2t]^2) + fl(x[2t+1]^2))
//   warp butterfly shfl_down 16,8,4,2,1 (all __fadd_rn)
//   8 warp partials -> smem -> warp 0 identity-padded butterfly.
// Must be called by all 256 threads of the block.
__device__ __forceinline__ float xla_rownorm512(const float* __restrict__ row,
                                                float* __restrict__ sh8) {
    int t = threadIdx.x;           // 0..255
    int lane = t & 31;
    int w = t >> 5;                // 0..7
    float2 e = *(const float2*)(row + 2 * t);
    float p = __fadd_rn(__fmul_rn(e.x, e.x), __fmul_rn(e.y, e.y));
#pragma unroll
    for (int off = 16; off; off >>= 1)
        p = __fadd_rn(p, __shfl_down_sync(0xFFFFFFFFu, p, off));
    if (lane == 0) sh8[w] = p;
    __syncthreads();
    float s = 0.0f;
    if (w == 0) {
        s = (lane < 8) ? sh8[lane] : 0.0f;
#pragma unroll
        for (int off = 16; off; off >>= 1)
            s = __fadd_rn(s, __shfl_down_sync(0xFFFFFFFFu, s, off));
    }
    return s;   // valid in thread 0 only
}

// ---------------- prep: codebook norms (XLA-order f32) + zero histogram ----------------
__global__ void __launch_bounds__(256) prep_kernel(const float* __restrict__ cb) {
    __shared__ float sh8[8];
    int code = blockIdx.x;                 // 0 .. L*K-1
    float s = xla_rownorm512(cb + (size_t)code * Dn, sh8);
    if (threadIdx.x == 0) {
        g_cnorm[code] = s;
        g_hist[code] = 0;
    }
}

// ---------------- per-level row norms (XLA-order f32) ----------------
__global__ void __launch_bounds__(256) xnorm_kernel(const float* __restrict__ out, int level) {
    __shared__ float sh8[8];
    int b = blockIdx.x;                    // 0 .. B-1
    float s = xla_rownorm512(out + OFF_R + ((size_t)b * Ln + level) * Dn, sh8);
    if (threadIdx.x == 0) g_xnorm[b] = s;
}

// ---------------- r[:,0,:] = x ----------------
__global__ void copy_r0_kernel(const float* __restrict__ x, float* __restrict__ out) {
    size_t t = (size_t)blockIdx.x * blockDim.x + threadIdx.x;  // B*D/4 threads
    int b = (int)(t >> 7);
    int d4 = ((int)t & 127) << 2;
    float4 v = *(const float4*)(x + (size_t)b * Dn + d4);
    *(float4*)(out + OFF_R + (size_t)b * Ln * Dn + d4) = v;
}

// ---------------- fused distance + argmin per level ----------------
constexpr int TM = 64;    // rows per block
constexpr int TN = 128;   // code chunk
constexpr int DKc = 32;   // D step
constexpr int XS_STRIDE = TM + 4;   // 68
constexpr int CS_STRIDE = TN + 4;   // 132

__global__ void __launch_bounds__(256)
argmin_kernel(float* __restrict__ out_base, const float* __restrict__ cb, int level) {
    __shared__ __align__(16) float xs[DKc * XS_STRIDE];   // [kk][row]
    __shared__ __align__(16) float cs[DKc * CS_STRIDE];   // [kk][code]

    const int tid = threadIdx.x;
    const int m0 = blockIdx.x * TM;
    const int tr = tid & 15;     // rows tr*4 .. tr*4+3
    const int tc = tid >> 4;     // codes tc*8 .. tc*8+7
    const float* __restrict__ cbl = cb + (size_t)level * Kn * Dn;
    const float* __restrict__ rbase = out_base + OFF_R + (size_t)level * Dn;
    const float* __restrict__ cn = g_cnorm + level * Kn;

    // per-row ||x||^2 (f32, XLA rounding) for the reference's combine order
    float xn[4];
#pragma unroll
    for (int r = 0; r < 4; r++) xn[r] = g_xnorm[m0 + tr * 4 + r];

    float best[4] = {FLT_MAX, FLT_MAX, FLT_MAX, FLT_MAX};
    int   bidx[4] = {0, 0, 0, 0};

    for (int kc = 0; kc < Kn; kc += TN) {
        unsigned long long acc[4][4];
#pragma unroll
        for (int r = 0; r < 4; r++)
#pragma unroll
            for (int c = 0; c < 4; c++) acc[r][c] = 0ULL;

        for (int dk = 0; dk < Dn; dk += DKc) {
            // prefetch globals into registers
            float4 xg[2], cg[4];
#pragma unroll
            for (int i = 0; i < 2; i++) {
                int q = tid + 256 * i;         // 0..511
                int row = q >> 3;
                int c4 = (q & 7) << 2;
                xg[i] = *(const float4*)(rbase + (size_t)(m0 + row) * Ln * Dn + dk + c4);
            }
#pragma unroll
            for (int i = 0; i < 4; i++) {
                int q = tid + 256 * i;         // 0..1023
                int code = q >> 3;
                int c4 = (q & 7) << 2;
                cg[i] = *(const float4*)(cbl + (size_t)(kc + code) * Dn + dk + c4);
            }
            __syncthreads();
#pragma unroll
            for (int i = 0; i < 2; i++) {
                int q = tid + 256 * i;
                int row = q >> 3;
                int c4 = (q & 7) << 2;
                xs[(c4 + 0) * XS_STRIDE + row] = xg[i].x;
                xs[(c4 + 1) * XS_STRIDE + row] = xg[i].y;
                xs[(c4 + 2) * XS_STRIDE + row] = xg[i].z;
                xs[(c4 + 3) * XS_STRIDE + row] = xg[i].w;
            }
#pragma unroll
            for (int i = 0; i < 4; i++) {
                int q = tid + 256 * i;
                int code = q >> 3;
                int c4 = (q & 7) << 2;
                cs[(c4 + 0) * CS_STRIDE + code] = cg[i].x;
                cs[(c4 + 1) * CS_STRIDE + code] = cg[i].y;
                cs[(c4 + 2) * CS_STRIDE + code] = cg[i].z;
                cs[(c4 + 3) * CS_STRIDE + code] = cg[i].w;
            }
            __syncthreads();
#pragma unroll
            for (int kk = 0; kk < DKc; kk++) {
                float4 xv = *(const float4*)&xs[kk * XS_STRIDE + tr * 4];
                ulonglong2 cc0 = *(const ulonglong2*)&cs[kk * CS_STRIDE + tc * 8];
                ulonglong2 cc1 = *(const ulonglong2*)&cs[kk * CS_STRIDE + tc * 8 + 4];
                unsigned long long dx0 = pack2(xv.x, xv.x);
                unsigned long long dx1 = pack2(xv.y, xv.y);
                unsigned long long dx2 = pack2(xv.z, xv.z);
                unsigned long long dx3 = pack2(xv.w, xv.w);
                acc[0][0] = fma2(dx0, cc0.x, acc[0][0]);
                acc[0][1] = fma2(dx0, cc0.y, acc[0][1]);
                acc[0][2] = fma2(dx0, cc1.x, acc[0][2]);
                acc[0][3] = fma2(dx0, cc1.y, acc[0][3]);
                acc[1][0] = fma2(dx1, cc0.x, acc[1][0]);
                acc[1][1] = fma2(dx1, cc0.y, acc[1][1]);
                acc[1][2] = fma2(dx1, cc1.x, acc[1][2]);
                acc[1][3] = fma2(dx1, cc1.y, acc[1][3]);
                acc[2][0] = fma2(dx2, cc0.x, acc[2][0]);
                acc[2][1] = fma2(dx2, cc0.y, acc[2][1]);
                acc[2][2] = fma2(dx2, cc1.x, acc[2][2]);
                acc[2][3] = fma2(dx2, cc1.y, acc[2][3]);
                acc[3][0] = fma2(dx3, cc0.x, acc[3][0]);
                acc[3][1] = fma2(dx3, cc0.y, acc[3][1]);
                acc[3][2] = fma2(dx3, cc1.x, acc[3][2]);
                acc[3][3] = fma2(dx3, cc1.y, acc[3][3]);
            }
        }
        // fold chunk scores into running argmin, replicating the reference's
        // elementwise rounding:  d = fl( fl(xx - fl(2*m)) + cc )
        // (ascending k + strict < keeps first index, matching jnp.argmin)
#pragma unroll
        for (int r = 0; r < 4; r++) {
#pragma unroll
            for (int cp = 0; cp < 4; cp++) {
                float m0v, m1v;
                unpack2(acc[r][cp], m0v, m1v);
                int k0 = kc + tc * 8 + cp * 2;
                float v0 = __fadd_rn(__fsub_rn(xn[r], __fmul_rn(2.0f, m0v)), cn[k0]);
                float v1 = __fadd_rn(__fsub_rn(xn[r], __fmul_rn(2.0f, m1v)), cn[k0 + 1]);
                if (v0 < best[r]) { best[r] = v0; bidx[r] = k0; }
                if (v1 < best[r]) { best[r] = v1; bidx[r] = k0 + 1; }
            }
        }
    }

    // cross-thread reduction: 64 rows x 16 candidates
    __syncthreads();
    float* rv = xs;          // 1024 floats, fits
    int* ri = (int*)cs;      // 1024 ints, fits
#pragma unroll
    for (int r = 0; r < 4; r++) {
        rv[(tr * 4 + r) * 16 + tc] = best[r];
        ri[(tr * 4 + r) * 16 + tc] = bidx[r];
    }
    __syncthreads();
    if (tid < TM) {
        float bv = rv[tid * 16];
        int bi = ri[tid * 16];
#pragma unroll
        for (int j = 1; j < 16; j++) {
            float v = rv[tid * 16 + j];
            int i2 = ri[tid * 16 + j];
            if (v < bv || (v == bv && i2 < bi)) { bv = v; bi = i2; }
        }
        int b = m0 + tid;
        g_idx[b * Ln + level] = bi;
        out_base[OFF_OUT + (size_t)b * Ln + level] = (float)bi;
        atomicAdd(&g_hist[level * Kn + bi], 1);
    }
}

// ---------------- gather e, compute next residual ----------------
__global__ void update_kernel(const float* __restrict__ cb, float* __restrict__ out, int level) {
    size_t t = (size_t)blockIdx.x * 256 + threadIdx.x;   // B*D/4
    int b = (int)(t >> 7);
    int d4 = ((int)t & 127) << 2;
    int idx = g_idx[b * Ln + level];
    const float* cbl = cb + ((size_t)level * Kn + idx) * Dn;
    float4 e = *(const float4*)(cbl + d4);
    size_t ro = ((size_t)b * Ln + level) * Dn + d4;
    *(float4*)(out + OFF_E + ro) = e;
    if (level < Ln - 1) {
        float4 r = *(const float4*)(out + OFF_R + ro);
        float4 rn = make_float4(__fsub_rn(r.x, e.x), __fsub_rn(r.y, e.y),
                                __fsub_rn(r.z, e.z), __fsub_rn(r.w, e.w));
        *(float4*)(out + OFF_R + ro + Dn) = rn;
    }
}

// ---------------- z_hat = x + (sum_l e_l - x) ----------------
__global__ void zhat_kernel(const float* __restrict__ x, float* __restrict__ out) {
    size_t t = (size_t)blockIdx.x * 256 + threadIdx.x;   // B*D/4
    int b = (int)(t >> 7);
    int d4 = ((int)t & 127) << 2;
    const float* eb = out + OFF_E + (size_t)b * Ln * Dn + d4;
    float4 e0 = *(const float4*)(eb);
    float4 e1 = *(const float4*)(eb + Dn);
    float4 e2 = *(const float4*)(eb + 2 * Dn);
    float4 e3 = *(const float4*)(eb + 3 * Dn);
    float4 xv = *(const float4*)(x + (size_t)b * Dn + d4);
    float4 z;
    z.x = __fadd_rn(xv.x, __fsub_rn(__fadd_rn(__fadd_rn(__fadd_rn(e0.x, e1.x), e2.x), e3.x), xv.x));
    z.y = __fadd_rn(xv.y, __fsub_rn(__fadd_rn(__fadd_rn(__fadd_rn(e0.y, e1.y), e2.y), e3.y), xv.y));
    z.z = __fadd_rn(xv.z, __fsub_rn(__fadd_rn(__fadd_rn(__fadd_rn(e0.z, e1.z), e2.z), e3.z), xv.z));
    z.w = __fadd_rn(xv.w, __fsub_rn(__fadd_rn(__fadd_rn(__fadd_rn(e0.w, e1.w), e2.w), e3.w), xv.w));
    *(float4*)(out + OFF_Z + (size_t)b * Dn + d4) = z;
}

// ---------------- unused-code count ----------------
__global__ void count_kernel(float* __restrict__ out) {
    int t = threadIdx.x;   // 256
    int c = 0;
    for (int i = t; i < Ln * Kn; i += 256)
        if (g_hist[i] == 0) c++;
    for (int o = 16; o; o >>= 1) c += __shfl_down_sync(0xFFFFFFFFu, c, o);
    __shared__ int ws[8];
    if ((t & 31) == 0) ws[t >> 5] = c;
    __syncthreads();
    if (t == 0) {
        int tot = 0;
        for (int j = 0; j < 8; j++) tot += ws[j];
        out[OFF_CNT] = (float)tot;
    }
}

extern "C" void kernel_launch(void* const* d_in, const int* in_sizes, int n_in,
                              void* d_out, int out_size) {
    const float* x  = (const float*)d_in[0];   // [B, D]
    const float* cb = (const float*)d_in[1];   // [L, K, D]
    float* out = (float*)d_out;

    prep_kernel<<<Ln * Kn, 256>>>(cb);
    copy_r0_kernel<<<(Bn * Dn / 4) / 256, 256>>>(x, out);
    for (int l = 0; l < Ln; l++) {
        xnorm_kernel<<<Bn, 256>>>(out, l);
        argmin_kernel<<<Bn / TM, 256>>>(out, cb, l);
        update_kernel<<<(Bn * Dn / 4) / 256, 256>>>(cb, out, l);
    }
    zhat_kernel<<<(Bn * Dn / 4) / 256, 256>>>(x, out);
    count_kernel<<<1, 256>>>(out);
}